// round 11
// baseline (speedup 1.0000x reference)
#include <cuda_runtime.h>
#include <cstdint>

// E[b] = sum over strict-lower-tri pairs (i,j) (row-major flat order):
//          decompFE_flat[b,p] * rsqrt(|coords[b,i]-coords[b,j]|^2)
//
// TMA bulk-copy of both flat rows into smem (copy-engine MLP), then fused
// loop where each lane owns a j-PAIR (j=2l, 2l+1) across 2 batches:
// 128 pairs per iteration amortize all loop/address/predicate scaffolding.

#define BATCH   2048
#define NATOMS  100
#define NC2     4950
#define TPB     256
#define NWARPS  (TPB / 32)
#define BPB     2
#define COPY_BYTES (BPB * NC2 * 4)      // 39600, multiple of 16

__device__ __forceinline__ uint32_t smem_u32(const void* p) {
    uint32_t a;
    asm("{ .reg .u64 t; cvta.to.shared.u64 t, %1; cvt.u32.u64 %0, t; }"
        : "=r"(a) : "l"(p));
    return a;
}

__global__ __launch_bounds__(TPB)
void eij_kernel(const float* __restrict__ coords,
                const float* __restrict__ flat,
                float* __restrict__ out)
{
    __shared__ float sflat[BPB * NC2];            // 39600 B
    __shared__ float sc[128 * 8];                 // [atom*8 + q*4 + c], padded
    __shared__ float wred[BPB][NWARPS];
    __shared__ __align__(8) unsigned long long mbar;

    const int b0   = blockIdx.x * BPB;
    const int t    = threadIdx.x;
    const int lane = t & 31;
    const int wid  = t >> 5;

    const uint32_t mb = smem_u32(&mbar);

    if (t == 0)
        asm volatile("mbarrier.init.shared.b64 [%0], 1;" :: "r"(mb) : "memory");
    __syncthreads();

    if (t == 0) {
        const uint32_t dst = smem_u32(sflat);
        const float* src = flat + (size_t)b0 * NC2;   // 39600B segment, 16B aligned
        asm volatile("mbarrier.arrive.expect_tx.shared.b64 _, [%0], %1;"
                     :: "r"(mb), "r"((unsigned)COPY_BYTES) : "memory");
        asm volatile("cp.async.bulk.shared::cta.global.mbarrier::complete_tx::bytes"
                     " [%0], [%1], %2, [%3];"
                     :: "r"(dst), "l"(src), "r"((unsigned)COPY_BYTES), "r"(mb)
                     : "memory");
    }

    // zero-pad + stage coords (interleaved [atom][q][4]) while the copy flies
    for (int k = t; k < 128 * 8; k += TPB) sc[k] = 0.0f;
    __syncthreads();
    for (int k = t; k < NATOMS * 3 * BPB; k += TPB) {
        const int q    = k / (NATOMS * 3);
        const int r    = k - q * (NATOMS * 3);
        const int atom = r / 3;
        const int c    = r - atom * 3;
        sc[atom * 8 + q * 4 + c] = coords[(size_t)(b0 + q) * (NATOMS * 3) + r];
    }
    __syncthreads();

    // wait for the flat tile
    {
        uint32_t done;
        do {
            asm volatile("{ .reg .pred p;"
                         "  mbarrier.try_wait.parity.shared.b64 p, [%1], 0, 0x989680;"
                         "  selp.b32 %0, 1, 0, p; }"
                         : "=r"(done) : "r"(mb) : "memory");
        } while (!done);
    }

    float a00 = 0.f, a01 = 0.f, a10 = 0.f, a11 = 0.f;  // [batch][jslot]

    #pragma unroll
    for (int jc = 0; jc < 2; ++jc) {
        const int jbase = jc * 64;
        const int j0 = jbase + 2 * lane;          // even j; j1 = j0+1

        // lane-resident coords for j0, j1 x 2 batches
        const float4 cA0 = *(const float4*)&sc[j0 * 8 + 0];
        const float4 cA1 = *(const float4*)&sc[j0 * 8 + 4];
        const float4 cB0 = *(const float4*)&sc[(j0 + 1) * 8 + 0];
        const float4 cB1 = *(const float4*)&sc[(j0 + 1) * 8 + 4];

        int i   = (jc == 0 ? 1 : 65) + wid;
        int off = i * (i - 1) / 2 + jbase + 2 * lane;

        #pragma unroll 2
        for (; i < NATOMS; off += 8 * i + 28, i += NWARPS) {
            const bool va = (j0     < i);
            const bool vb = (j0 + 1 < i);

            float v00 = 0.f, v01 = 0.f, v10 = 0.f, v11 = 0.f;
            if (va) { v00 = sflat[off];     v10 = sflat[off + NC2];     }
            if (vb) { v01 = sflat[off + 1]; v11 = sflat[off + NC2 + 1]; }

            const float4 ci0 = *(const float4*)&sc[i * 8 + 0];  // batch0 i
            const float4 ci1 = *(const float4*)&sc[i * 8 + 4];  // batch1 i

            // batch 0, j0
            float dx = ci0.x - cA0.x, dy = ci0.y - cA0.y, dz = ci0.z - cA0.z;
            float r2 = fmaf(dx, dx, fmaf(dy, dy, dz * dz));
            if (va) a00 = fmaf(v00, rsqrtf(r2), a00);
            // batch 0, j1
            dx = ci0.x - cB0.x; dy = ci0.y - cB0.y; dz = ci0.z - cB0.z;
            r2 = fmaf(dx, dx, fmaf(dy, dy, dz * dz));
            if (vb) a01 = fmaf(v01, rsqrtf(r2), a01);
            // batch 1, j0
            dx = ci1.x - cA1.x; dy = ci1.y - cA1.y; dz = ci1.z - cA1.z;
            r2 = fmaf(dx, dx, fmaf(dy, dy, dz * dz));
            if (va) a10 = fmaf(v10, rsqrtf(r2), a10);
            // batch 1, j1
            dx = ci1.x - cB1.x; dy = ci1.y - cB1.y; dz = ci1.z - cB1.z;
            r2 = fmaf(dx, dx, fmaf(dy, dy, dz * dz));
            if (vb) a11 = fmaf(v11, rsqrtf(r2), a11);
        }
    }

    float acc0 = a00 + a01;
    float acc1 = a10 + a11;

    // reductions
    #pragma unroll
    for (int off = 16; off > 0; off >>= 1) {
        acc0 += __shfl_down_sync(0xFFFFFFFFu, acc0, off);
        acc1 += __shfl_down_sync(0xFFFFFFFFu, acc1, off);
    }
    if (lane == 0) { wred[0][wid] = acc0; wred[1][wid] = acc1; }
    __syncthreads();

    if (wid == 0 && lane < NWARPS) {
        float s0 = wred[0][lane];
        float s1 = wred[1][lane];
        #pragma unroll
        for (int off = NWARPS / 2; off > 0; off >>= 1) {
            s0 += __shfl_down_sync(0xFFu, s0, off);
            s1 += __shfl_down_sync(0xFFu, s1, off);
        }
        if (lane == 0) { out[b0] = s0; out[b0 + 1] = s1; }
    }
}

extern "C" void kernel_launch(void* const* d_in, const int* in_sizes, int n_in,
                              void* d_out, int out_size)
{
    const float* coords = (const float*)d_in[0];   // [2048, 100, 3]
    const float* flat   = (const float*)d_in[1];   // [2048, 4950]
    float* out          = (float*)d_out;           // [2048, 1]

    eij_kernel<<<BATCH / BPB, TPB>>>(coords, flat, out);
}

// round 12
// speedup vs baseline: 1.2243x; 1.2243x over previous
#include <cuda_runtime.h>
#include <cstdint>

// E[b] = sum over strict-lower-tri pairs (i,j) (row-major flat order):
//          decompFE_flat[b,p] * rsqrt(|coords[b,i]-coords[b,j]|^2)
//
// R10 structure (TMA bulk-copy of both flat rows into smem; fused loop with
// lane-resident j coords and v from SMEM) but TPB=512: 4 blocks/SM at the
// 2048-thread cap -> 64 warps/SM resident, double R10's latency hiding.

#define BATCH   2048
#define NATOMS  100
#define NC2     4950
#define TPB     512
#define NWARPS  (TPB / 32)
#define BPB     2
#define COPY_BYTES (BPB * NC2 * 4)      // 39600, multiple of 16

__device__ __forceinline__ uint32_t smem_u32(const void* p) {
    uint32_t a;
    asm("{ .reg .u64 t; cvta.to.shared.u64 t, %1; cvt.u32.u64 %0, t; }"
        : "=r"(a) : "l"(p));
    return a;
}

__global__ __launch_bounds__(TPB, 4)
void eij_kernel(const float* __restrict__ coords,
                const float* __restrict__ flat,
                float* __restrict__ out)
{
    __shared__ float sflat[BPB * NC2];            // 39600 B
    __shared__ float sc[NATOMS * 8];              // [atom*8 + q*4 + c]
    __shared__ float wred[BPB][NWARPS];
    __shared__ __align__(8) unsigned long long mbar;

    const int b0   = blockIdx.x * BPB;
    const int t    = threadIdx.x;
    const int lane = t & 31;
    const int wid  = t >> 5;

    const uint32_t mb = smem_u32(&mbar);

    if (t == 0)
        asm volatile("mbarrier.init.shared.b64 [%0], 1;" :: "r"(mb) : "memory");
    __syncthreads();

    if (t == 0) {
        const uint32_t dst = smem_u32(sflat);
        const float* src = flat + (size_t)b0 * NC2;   // 16B-aligned segment
        asm volatile("mbarrier.arrive.expect_tx.shared.b64 _, [%0], %1;"
                     :: "r"(mb), "r"((unsigned)COPY_BYTES) : "memory");
        asm volatile("cp.async.bulk.shared::cta.global.mbarrier::complete_tx::bytes"
                     " [%0], [%1], %2, [%3];"
                     :: "r"(dst), "l"(src), "r"((unsigned)COPY_BYTES), "r"(mb)
                     : "memory");
    }

    // stage coords (interleaved [atom][q][4]) while the bulk copy flies
    for (int k = t; k < NATOMS * 3 * BPB; k += TPB) {
        const int q    = k / (NATOMS * 3);
        const int r    = k - q * (NATOMS * 3);
        const int atom = r / 3;
        const int c    = r - atom * 3;
        sc[atom * 8 + q * 4 + c] = coords[(size_t)(b0 + q) * (NATOMS * 3) + r];
    }
    __syncthreads();

    // wait for the flat tile
    {
        uint32_t done;
        do {
            asm volatile("{ .reg .pred p;"
                         "  mbarrier.try_wait.parity.shared.b64 p, [%1], 0, 0x989680;"
                         "  selp.b32 %0, 1, 0, p; }"
                         : "=r"(done) : "r"(mb) : "memory");
        } while (!done);
    }

    float acc0 = 0.0f, acc1 = 0.0f;

    #pragma unroll
    for (int jb = 0; jb < 4; ++jb) {
        const int jbase = jb * 32;
        const int j = jbase + lane;

        float xj0 = 0.f, yj0 = 0.f, zj0 = 0.f;
        float xj1 = 0.f, yj1 = 0.f, zj1 = 0.f;
        if (j < NATOMS) {
            const float4 c0 = *(const float4*)&sc[j * 8 + 0];
            const float4 c1 = *(const float4*)&sc[j * 8 + 4];
            xj0 = c0.x; yj0 = c0.y; zj0 = c0.z;
            xj1 = c1.x; yj1 = c1.y; zj1 = c1.z;
        }

        int i   = jbase + 1 + wid;
        int off = i * (i - 1) / 2 + jbase + lane;

        #pragma unroll 3
        for (; i < NATOMS;
               off += NWARPS * i + (NWARPS * (NWARPS - 1)) / 2, i += NWARPS) {
            const bool valid = lane < (i - jbase);

            float v0 = 0.0f, v1 = 0.0f;
            if (valid) {
                v0 = sflat[off];
                v1 = sflat[off + NC2];
            }

            const float4 ci0 = *(const float4*)&sc[i * 8 + 0];
            const float4 ci1 = *(const float4*)&sc[i * 8 + 4];

            float dx0 = ci0.x - xj0, dy0 = ci0.y - yj0, dz0 = ci0.z - zj0;
            float dx1 = ci1.x - xj1, dy1 = ci1.y - yj1, dz1 = ci1.z - zj1;
            float r20 = fmaf(dx0, dx0, fmaf(dy0, dy0, dz0 * dz0));
            float r21 = fmaf(dx1, dx1, fmaf(dy1, dy1, dz1 * dz1));

            if (valid) {
                acc0 = fmaf(v0, rsqrtf(r20), acc0);
                acc1 = fmaf(v1, rsqrtf(r21), acc1);
            }
        }
    }

    // reductions
    #pragma unroll
    for (int off = 16; off > 0; off >>= 1) {
        acc0 += __shfl_down_sync(0xFFFFFFFFu, acc0, off);
        acc1 += __shfl_down_sync(0xFFFFFFFFu, acc1, off);
    }
    if (lane == 0) { wred[0][wid] = acc0; wred[1][wid] = acc1; }
    __syncthreads();

    if (wid == 0 && lane < NWARPS) {
        float s0 = wred[0][lane];
        float s1 = wred[1][lane];
        #pragma unroll
        for (int off = NWARPS / 2; off > 0; off >>= 1) {
            s0 += __shfl_down_sync(0xFFFFu, s0, off);
            s1 += __shfl_down_sync(0xFFFFu, s1, off);
        }
        if (lane == 0) { out[b0] = s0; out[b0 + 1] = s1; }
    }
}

extern "C" void kernel_launch(void* const* d_in, const int* in_sizes, int n_in,
                              void* d_out, int out_size)
{
    const float* coords = (const float*)d_in[0];   // [2048, 100, 3]
    const float* flat   = (const float*)d_in[1];   // [2048, 4950]
    float* out          = (float*)d_out;           // [2048, 1]

    eij_kernel<<<BATCH / BPB, TPB>>>(coords, flat, out);
}

// round 13
// speedup vs baseline: 1.2429x; 1.0152x over previous
#include <cuda_runtime.h>
#include <cstdint>

// E[b] = sum over strict-lower-tri pairs (i,j) (row-major flat order):
//          decompFE_flat[b,p] * rsqrt(|coords[b,i]-coords[b,j]|^2)
//
// TMA bulk-copy of both flat rows into (padded) smem; TPB=512 for 64 warps/SM.
// Inner loop is fully branch-free: all loads unconditional (padded arrays),
// only the two accumulate FFMAs are predicated; off maintained incrementally.

#define BATCH   2048
#define NATOMS  100
#define NC2     4950
#define TPB     512
#define NWARPS  (TPB / 32)
#define BPB     2
#define COPY_BYTES (BPB * NC2 * 4)      // 39600, multiple of 16

__device__ __forceinline__ uint32_t smem_u32(const void* p) {
    uint32_t a;
    asm("{ .reg .u64 t; cvta.to.shared.u64 t, %1; cvt.u32.u64 %0, t; }"
        : "=r"(a) : "l"(p));
    return a;
}

__global__ __launch_bounds__(TPB, 4)
void eij_kernel(const float* __restrict__ coords,
                const float* __restrict__ flat,
                float* __restrict__ out)
{
    __shared__ float sflat[BPB * NC2 + 64];       // padded: OOB lanes stay in-bounds
    __shared__ float sc[128 * 8];                 // padded to 128 atoms, zero-filled
    __shared__ float wred[BPB][NWARPS];
    __shared__ __align__(8) unsigned long long mbar;

    const int b0   = blockIdx.x * BPB;
    const int t    = threadIdx.x;
    const int lane = t & 31;
    const int wid  = t >> 5;

    const uint32_t mb = smem_u32(&mbar);

    if (t == 0)
        asm volatile("mbarrier.init.shared.b64 [%0], 1;" :: "r"(mb) : "memory");
    __syncthreads();

    if (t == 0) {
        const uint32_t dst = smem_u32(sflat);
        const float* src = flat + (size_t)b0 * NC2;   // 16B-aligned segment
        asm volatile("mbarrier.arrive.expect_tx.shared.b64 _, [%0], %1;"
                     :: "r"(mb), "r"((unsigned)COPY_BYTES) : "memory");
        asm volatile("cp.async.bulk.shared::cta.global.mbarrier::complete_tx::bytes"
                     " [%0], [%1], %2, [%3];"
                     :: "r"(dst), "l"(src), "r"((unsigned)COPY_BYTES), "r"(mb)
                     : "memory");
    }

    // zero-pad coords then stage (interleaved [atom][q][4]) while copy flies
    for (int k = t; k < 128 * 8; k += TPB) sc[k] = 0.0f;
    __syncthreads();
    for (int k = t; k < NATOMS * 3 * BPB; k += TPB) {
        const int q    = k / (NATOMS * 3);
        const int r    = k - q * (NATOMS * 3);
        const int atom = r / 3;
        const int c    = r - atom * 3;
        sc[atom * 8 + q * 4 + c] = coords[(size_t)(b0 + q) * (NATOMS * 3) + r];
    }
    __syncthreads();

    // wait for the flat tile
    {
        uint32_t done;
        do {
            asm volatile("{ .reg .pred p;"
                         "  mbarrier.try_wait.parity.shared.b64 p, [%1], 0, 0x989680;"
                         "  selp.b32 %0, 1, 0, p; }"
                         : "=r"(done) : "r"(mb) : "memory");
        } while (!done);
    }

    float acc0 = 0.0f, acc1 = 0.0f;

    #pragma unroll
    for (int jb = 0; jb < 4; ++jb) {
        const int jbase = jb * 32;
        const int j = jbase + lane;       // may be >= NATOMS; sc padded

        const float4 c0 = *(const float4*)&sc[j * 8 + 0];
        const float4 c1 = *(const float4*)&sc[j * 8 + 4];
        const float xj0 = c0.x, yj0 = c0.y, zj0 = c0.z;
        const float xj1 = c1.x, yj1 = c1.y, zj1 = c1.z;

        int i    = jbase + 1 + wid;
        int off  = i * (i - 1) / 2 + jbase + lane;
        int step = NWARPS * i + (NWARPS * (NWARPS - 1)) / 2;

        #pragma unroll 2
        for (; i < NATOMS; i += NWARPS) {
            const bool valid = lane < (i - jbase);

            // unconditional loads (arrays padded)
            const float v0 = sflat[off];
            const float v1 = sflat[off + NC2];

            const float4 ci0 = *(const float4*)&sc[i * 8 + 0];
            const float4 ci1 = *(const float4*)&sc[i * 8 + 4];

            const float dx0 = ci0.x - xj0, dy0 = ci0.y - yj0, dz0 = ci0.z - zj0;
            const float dx1 = ci1.x - xj1, dy1 = ci1.y - yj1, dz1 = ci1.z - zj1;
            const float r20 = fmaf(dx0, dx0, fmaf(dy0, dy0, dz0 * dz0));
            const float r21 = fmaf(dx1, dx1, fmaf(dy1, dy1, dz1 * dz1));

            const float rr0 = rsqrtf(r20);
            const float rr1 = rsqrtf(r21);

            // single-statement ifs -> predicated @P FFMA (no branch)
            if (valid) acc0 = fmaf(v0, rr0, acc0);
            if (valid) acc1 = fmaf(v1, rr1, acc1);

            off  += step;
            step += NWARPS * NWARPS;
        }
    }

    // reductions
    #pragma unroll
    for (int off = 16; off > 0; off >>= 1) {
        acc0 += __shfl_down_sync(0xFFFFFFFFu, acc0, off);
        acc1 += __shfl_down_sync(0xFFFFFFFFu, acc1, off);
    }
    if (lane == 0) { wred[0][wid] = acc0; wred[1][wid] = acc1; }
    __syncthreads();

    if (wid == 0 && lane < NWARPS) {
        float s0 = wred[0][lane];
        float s1 = wred[1][lane];
        #pragma unroll
        for (int off = NWARPS / 2; off > 0; off >>= 1) {
            s0 += __shfl_down_sync(0xFFFFu, s0, off);
            s1 += __shfl_down_sync(0xFFFFu, s1, off);
        }
        if (lane == 0) { out[b0] = s0; out[b0 + 1] = s1; }
    }
}

extern "C" void kernel_launch(void* const* d_in, const int* in_sizes, int n_in,
                              void* d_out, int out_size)
{
    const float* coords = (const float*)d_in[0];   // [2048, 100, 3]
    const float* flat   = (const float*)d_in[1];   // [2048, 4950]
    float* out          = (float*)d_out;           // [2048, 1]

    eij_kernel<<<BATCH / BPB, TPB>>>(coords, flat, out);
}

// round 14
// speedup vs baseline: 1.4086x; 1.1333x over previous
#include <cuda_runtime.h>
#include <cstdint>

// E[b] = sum over strict-lower-tri pairs (i,j) (row-major flat order):
//          decompFE_flat[b,p] * rsqrt(|coords[b,i]-coords[b,j]|^2)
//
// r^2 computed in FMA form: r2 = ni + nj - 2*ci.cj, with i-side coords staged
// as (-2x,-2y,-2z,n) and j-side as (x,y,z,n): 4 FP ops/batch instead of 6.
// Diagonal (masked) rows and full rows in separate loops: full-row majority
// path has no predication at all. TMA bulk-copy stages both flat rows.

#define BATCH   2048
#define NATOMS  100
#define NC2     4950
#define TPB     512
#define NWARPS  (TPB / 32)
#define BPB     2
#define COPY_BYTES (BPB * NC2 * 4)      // 39600, multiple of 16

__device__ __forceinline__ uint32_t smem_u32(const void* p) {
    uint32_t a;
    asm("{ .reg .u64 t; cvta.to.shared.u64 t, %1; cvt.u32.u64 %0, t; }"
        : "=r"(a) : "l"(p));
    return a;
}

__global__ __launch_bounds__(TPB, 4)
void eij_kernel(const float* __restrict__ coords,
                const float* __restrict__ flat,
                float* __restrict__ out)
{
    __shared__ float sflat[BPB * NC2 + 64];   // 39856 B, padded
    __shared__ float scA[128 * 8];            // i-side: (-2x,-2y,-2z,n) x 2 batches
    __shared__ float scB[128 * 8];            // j-side: ( x,  y,  z, n) x 2 batches
    __shared__ float wred[BPB][NWARPS];
    __shared__ __align__(8) unsigned long long mbar;

    const int b0   = blockIdx.x * BPB;
    const int t    = threadIdx.x;
    const int lane = t & 31;
    const int wid  = t >> 5;

    const uint32_t mb = smem_u32(&mbar);

    if (t == 0)
        asm volatile("mbarrier.init.shared.b64 [%0], 1;" :: "r"(mb) : "memory");
    __syncthreads();

    if (t == 0) {
        const uint32_t dst = smem_u32(sflat);
        const float* src = flat + (size_t)b0 * NC2;   // 16B-aligned segment
        asm volatile("mbarrier.arrive.expect_tx.shared.b64 _, [%0], %1;"
                     :: "r"(mb), "r"((unsigned)COPY_BYTES) : "memory");
        asm volatile("cp.async.bulk.shared::cta.global.mbarrier::complete_tx::bytes"
                     " [%0], [%1], %2, [%3];"
                     :: "r"(dst), "l"(src), "r"((unsigned)COPY_BYTES), "r"(mb)
                     : "memory");
    }

    // stage coords: one (atom, q) item per thread; pad atoms >= NATOMS with 0
    for (int k = t; k < 128 * BPB; k += TPB) {
        const int atom = k >> 1;
        const int q    = k & 1;
        float x = 0.f, y = 0.f, z = 0.f;
        if (atom < NATOMS) {
            const float* cp = coords + (size_t)(b0 + q) * (NATOMS * 3) + atom * 3;
            x = cp[0]; y = cp[1]; z = cp[2];
        }
        const float n = fmaf(x, x, fmaf(y, y, z * z));
        *(float4*)&scB[atom * 8 + q * 4] = make_float4(x, y, z, n);
        *(float4*)&scA[atom * 8 + q * 4] = make_float4(-2.f * x, -2.f * y, -2.f * z, n);
    }
    __syncthreads();

    // wait for the flat tile
    {
        uint32_t done;
        do {
            asm volatile("{ .reg .pred p;"
                         "  mbarrier.try_wait.parity.shared.b64 p, [%1], 0, 0x989680;"
                         "  selp.b32 %0, 1, 0, p; }"
                         : "=r"(done) : "r"(mb) : "memory");
        } while (!done);
    }

    float acc0 = 0.0f, acc1 = 0.0f;

    #pragma unroll
    for (int jb = 0; jb < 4; ++jb) {
        const int jbase = jb * 32;
        const int j = jbase + lane;       // may exceed NATOMS; arrays padded

        const float4 cj0 = *(const float4*)&scB[j * 8 + 0];
        const float4 cj1 = *(const float4*)&scB[j * 8 + 4];

        // ---- diagonal rows: i in [jbase+1, min(jbase+32, 99)], masked ----
        {
            int i    = jbase + 1 + wid;
            int off  = i * (i - 1) / 2 + jbase + lane;
            int step = NWARPS * i + (NWARPS * (NWARPS - 1)) / 2;
            const int iend = (jbase + 32 < NATOMS) ? jbase + 32 : NATOMS - 1;

            #pragma unroll 2
            for (; i <= iend; i += NWARPS) {
                const bool valid = lane < (i - jbase);

                const float v0 = sflat[off];
                const float v1 = sflat[off + NC2];

                const float4 ai0 = *(const float4*)&scA[i * 8 + 0];
                const float4 ai1 = *(const float4*)&scA[i * 8 + 4];

                const float r20 = fmaf(ai0.x, cj0.x, fmaf(ai0.y, cj0.y,
                                  fmaf(ai0.z, cj0.z, ai0.w + cj0.w)));
                const float r21 = fmaf(ai1.x, cj1.x, fmaf(ai1.y, cj1.y,
                                  fmaf(ai1.z, cj1.z, ai1.w + cj1.w)));

                const float rr0 = rsqrtf(r20);
                const float rr1 = rsqrtf(r21);

                if (valid) acc0 = fmaf(v0, rr0, acc0);
                if (valid) acc1 = fmaf(v1, rr1, acc1);

                off  += step;
                step += NWARPS * NWARPS;
            }
        }

        // ---- full rows: i in [jbase+33, 99], unmasked ----
        {
            int i    = jbase + 33 + wid;
            int off  = i * (i - 1) / 2 + jbase + lane;
            int step = NWARPS * i + (NWARPS * (NWARPS - 1)) / 2;

            #pragma unroll 2
            for (; i < NATOMS; i += NWARPS) {
                const float v0 = sflat[off];
                const float v1 = sflat[off + NC2];

                const float4 ai0 = *(const float4*)&scA[i * 8 + 0];
                const float4 ai1 = *(const float4*)&scA[i * 8 + 4];

                const float r20 = fmaf(ai0.x, cj0.x, fmaf(ai0.y, cj0.y,
                                  fmaf(ai0.z, cj0.z, ai0.w + cj0.w)));
                const float r21 = fmaf(ai1.x, cj1.x, fmaf(ai1.y, cj1.y,
                                  fmaf(ai1.z, cj1.z, ai1.w + cj1.w)));

                acc0 = fmaf(v0, rsqrtf(r20), acc0);
                acc1 = fmaf(v1, rsqrtf(r21), acc1);

                off  += step;
                step += NWARPS * NWARPS;
            }
        }
    }

    // reductions
    #pragma unroll
    for (int off = 16; off > 0; off >>= 1) {
        acc0 += __shfl_down_sync(0xFFFFFFFFu, acc0, off);
        acc1 += __shfl_down_sync(0xFFFFFFFFu, acc1, off);
    }
    if (lane == 0) { wred[0][wid] = acc0; wred[1][wid] = acc1; }
    __syncthreads();

    if (wid == 0 && lane < NWARPS) {
        float s0 = wred[0][lane];
        float s1 = wred[1][lane];
        #pragma unroll
        for (int off = NWARPS / 2; off > 0; off >>= 1) {
            s0 += __shfl_down_sync(0xFFFFu, s0, off);
            s1 += __shfl_down_sync(0xFFFFu, s1, off);
        }
        if (lane == 0) { out[b0] = s0; out[b0 + 1] = s1; }
    }
}

extern "C" void kernel_launch(void* const* d_in, const int* in_sizes, int n_in,
                              void* d_out, int out_size)
{
    const float* coords = (const float*)d_in[0];   // [2048, 100, 3]
    const float* flat   = (const float*)d_in[1];   // [2048, 4950]
    float* out          = (float*)d_out;           // [2048, 1]

    eij_kernel<<<BATCH / BPB, TPB>>>(coords, flat, out);
}